// round 9
// baseline (speedup 1.0000x reference)
#include <cuda_runtime.h>
#include <math.h>

// ---------------------------------------------------------------------------
// GAT_652835029007 — round 9 (= round 7 kernel, third submit; two infra fails).
//   init -> bar1 -> { va-blocks: compute va1/va2/vb (arrive-only at bar2),
//                     scan-blocks: P1 edge_out scan -> bar2 -> P2 edge_in }
//   -> bar3 -> P4 per-S1-node agg+LN+ELU -> bar4 -> P6 final -> arrive.
// ---------------------------------------------------------------------------

#define NNODE 20001
#define LASTN 20000
#define INF   256
#define HID   128
#define NH    4
#define HD    512
#define NB    2
#define NE    500000
#define NE8   62500
#define BMW   626
#define MAX_D2    512
#define MAX_E1    65536
#define MAX_S1    1024
#define MAX_MATCH 512
#define NVA   14          // blocks dedicated to va precompute during scans
#define INV_SCALE 0.044194173824159216f   // 1/sqrt(512)

// ------------------------------- scratch -----------------------------------
__device__ unsigned g_bar;                 // zero-init; reset by last arriver
__device__ int      g_d2_cnt[NB];
__device__ int      g_d2_dst[NB][MAX_D2];
__device__ unsigned g_s1_bm[NB][BMW];
__device__ int      g_s1_cnt[NB];
__device__ int      g_s1_list[NB][MAX_S1];
__device__ int      g_s1_idx[NB][NNODE];
__device__ int      g_e1_cnt[NB];
__device__ int      g_e1_src[NB][MAX_E1], g_e1_dst[NB][MAX_E1];
__device__ __align__(16) float g_hln[NB][MAX_S1][HD];
__device__ __align__(16) float g_va1[8][INF];   // [h]=src-half, [4+h]=dst-half
__device__ __align__(16) float g_va2[8][HD];
__device__ float    g_vb1[8], g_vb2[8];

// ------------------------------- helpers -----------------------------------
__device__ __forceinline__ float dot44(float4 a, float4 b) {
    return a.x * b.x + a.y * b.y + a.z * b.z + a.w * b.w;
}

__device__ __forceinline__ void warpsum4(float& a, float& b, float& c, float& d) {
#pragma unroll
    for (int off = 16; off; off >>= 1) {
        a += __shfl_xor_sync(0xffffffffu, a, off);
        b += __shfl_xor_sync(0xffffffffu, b, off);
        c += __shfl_xor_sync(0xffffffffu, c, off);
        d += __shfl_xor_sync(0xffffffffu, d, off);
    }
}

__device__ __forceinline__ float blockreduce256(float v, float* sred) {
    int t = threadIdx.x;
    sred[t] = v; __syncthreads();
#pragma unroll
    for (int s = 128; s > 0; s >>= 1) {
        if (t < s) sred[t] += sred[t + s];
        __syncthreads();
    }
    float r = sred[0]; __syncthreads();
    return r;
}

__device__ __forceinline__ void gbar_arrive() {
    __syncthreads();
    if (threadIdx.x == 0) {
        __threadfence();
        atomicAdd(&g_bar, 1u);
    }
    __syncthreads();
}

__device__ __forceinline__ void gbar(unsigned target) {
    __syncthreads();
    if (threadIdx.x == 0) {
        __threadfence();
        atomicAdd(&g_bar, 1u);
        while (*(volatile unsigned*)&g_bar < target) __nanosleep(32);
        __threadfence();
    }
    __syncthreads();
}

// ------------------------------- fused kernel -------------------------------
__global__ void __launch_bounds__(256, 2) fused(
    const int* __restrict__ ei, const int* __restrict__ eo,
    const float* __restrict__ embed,
    const float* __restrict__ W1, const float* __restrict__ b1,
    const float* __restrict__ a1,
    const float* __restrict__ g1, const float* __restrict__ bn1,
    const float* __restrict__ W2, const float* __restrict__ b2,
    const float* __restrict__ a2,
    const float* __restrict__ g2, const float* __restrict__ bn2,
    const float* __restrict__ Vw, const float* __restrict__ Vb,
    float* __restrict__ out)
{
    int t = threadIdx.x;
    int lane = t & 31, wid = t >> 5;
    unsigned nb = gridDim.x;
    int bi = blockIdx.x;
    int gtid = bi * 256 + t;
    int nth = nb * 256;

    __shared__ __align__(16) float s_red[256];
    __shared__ float s_rs[NH], s_rsT[NH];
    __shared__ int   s_mcnt;
    __shared__ __align__(16) float s_va1[8][INF];        // 8KB, P4 only
    __shared__ float s_vb1s[8];
    __shared__ __align__(16) char s_mem[20480];
    // P4 views
    int*   s_md = (int*)s_mem;                           // [512]      2KB
    float (*s_me)[NH] = (float(*)[NH])(s_mem + 2048);    // [512][4]   8KB
    float (*s_z)[INF] = (float(*)[INF])(s_mem + 10240);  // [4][256]   4KB
    float* s_ov = (float*)(s_mem + 14336);               // [512]      2KB
    // P6 views
    float (*s_z2)[HD] = (float(*)[HD])(s_mem);           // [4][512]   8KB
    float (*s_e2)[NH] = (float(*)[NH])(s_mem + 8192);    // [512][4]   8KB
    int*   s_md2 = (int*)(s_mem + 16384);                // [512]      2KB
    float* s_hp2 = s_ov;

    // ===================== init (all blocks, tiny) ==========================
    for (int i = gtid; i < NB * BMW; i += nth) {
        int b = i / BMW, w = i - b * BMW;
        g_s1_bm[b][w] = (w == (LASTN >> 5)) ? (1u << (LASTN & 31)) : 0u;
    }
    if (bi == nb - 1 && t == 0) {
        for (int b = 0; b < NB; b++) {
            g_d2_cnt[b] = 0; g_e1_cnt[b] = 0;
            g_s1_cnt[b] = 1;
            g_s1_list[b][0] = LASTN; g_s1_idx[b][LASTN] = 0;
        }
    }
    gbar(1u * nb);

    // ===================== window 1+2: va blocks vs scan blocks =============
    if (bi < NVA) {
        // arrive-only at bar2: nothing in P1/P2 depends on va outputs.
        gbar_arrive();
        if (bi < 4) {
            // va1 for head h=bi: thread k in 0..255, both sd halves at once
            int h = bi, k = t;
            const float* W = W1 + (size_t)h * HID * INF + k;
            const float* as = a1 + h * 2 * HID;
            const float* ad = as + HID;
            float s0 = 0.f, s1_ = 0.f, d0 = 0.f, d1_ = 0.f;
#pragma unroll 16
            for (int o = 0; o < HID; o += 2) {
                float w0 = W[(o + 0) * INF];
                float w1 = W[(o + 1) * INF];
                s0 += w0 * as[o]; s1_ += w1 * as[o + 1];
                d0 += w0 * ad[o]; d1_ += w1 * ad[o + 1];
            }
            g_va1[h][k] = s0 + s1_;
            g_va1[4 + h][k] = d0 + d1_;
        } else if (bi < 12) {
            // va2: block (bi-4) = h*2 + khalf; thread k = khalf*256+t
            int u = bi - 4;
            int h = u >> 1, k = (u & 1) * 256 + t;
            const float* W = W2 + (size_t)h * HID * HD + k;
            const float* as = a2 + h * 2 * HID;
            const float* ad = as + HID;
            float s0 = 0.f, s1_ = 0.f, d0 = 0.f, d1_ = 0.f;
#pragma unroll 16
            for (int o = 0; o < HID; o += 2) {
                float w0 = W[(o + 0) * HD];
                float w1 = W[(o + 1) * HD];
                s0 += w0 * as[o]; s1_ += w1 * as[o + 1];
                d0 += w0 * ad[o]; d1_ += w1 * ad[o + 1];
            }
            g_va2[h][k] = s0 + s1_;
            g_va2[4 + h][k] = d0 + d1_;
        } else {
            // vb1 (bi==12) / vb2 (bi==13): warp w -> idx w (idx = sd*4+h)
            int which = (bi == 13);
            int idx = wid, h = idx & 3, sd = idx >> 2;
            const float* bb = (which ? b2 : b1) + h * HID;
            const float* av = (which ? a2 : a1) + h * 2 * HID + sd * HID;
            float p = 0.f;
            for (int o = lane; o < HID; o += 32) p += bb[o] * av[o];
#pragma unroll
            for (int off = 16; off; off >>= 1) p += __shfl_xor_sync(0xffffffffu, p, off);
            if (lane == 0) { if (which) g_vb2[idx] = p; else g_vb1[idx] = p; }
        }
        // full arrive+wait at bar3 (va results now published)
        gbar(3u * nb);
    } else {
        int sid = (bi - NVA) * 256 + t;
        int snth = (nb - NVA) * 256;

        // -------- P1: scan edge_out for src == LASTN (8 ints/iter) ----------
        for (int u = sid; u < NB * NE8; u += snth) {
            int b = (u >= NE8);
            int i8 = (b ? u - NE8 : u) * 8;
            const int* base = eo + (size_t)b * 2 * NE;
            int4 sA = *(const int4*)(base + i8);
            int4 sB = *(const int4*)(base + i8 + 4);
            int sv[8] = {sA.x, sA.y, sA.z, sA.w, sB.x, sB.y, sB.z, sB.w};
#pragma unroll
            for (int j = 0; j < 8; j++) {
                if (sv[j] == LASTN) {
                    int dst = base[NE + i8 + j];
                    int p = atomicAdd(&g_d2_cnt[b], 1);
                    if (p < MAX_D2) g_d2_dst[b][p] = dst;
                    unsigned m = 1u << (dst & 31);
                    unsigned old = atomicOr(&g_s1_bm[b][dst >> 5], m);
                    if (!(old & m)) {
                        int q = atomicAdd(&g_s1_cnt[b], 1);
                        if (q < MAX_S1) { g_s1_list[b][q] = dst; g_s1_idx[b][dst] = q; }
                    }
                }
            }
        }
        gbar(2u * nb);

        // -------- P2: scan edge_in for src in S1 (8 ints/iter) --------------
        for (int u = sid; u < NB * NE8; u += snth) {
            int b = (u >= NE8);
            int i8 = (b ? u - NE8 : u) * 8;
            const int* base = ei + (size_t)b * 2 * NE;
            int4 sA = *(const int4*)(base + i8);
            int4 sB = *(const int4*)(base + i8 + 4);
            int sv[8] = {sA.x, sA.y, sA.z, sA.w, sB.x, sB.y, sB.z, sB.w};
#pragma unroll
            for (int j = 0; j < 8; j++) {
                int s = sv[j];
                if ((g_s1_bm[b][s >> 5] >> (s & 31)) & 1u) {
                    int p = atomicAdd(&g_e1_cnt[b], 1);
                    if (p < MAX_E1) {
                        g_e1_src[b][p] = s;
                        g_e1_dst[b][p] = base[NE + i8 + j];
                    }
                }
            }
        }
        gbar(3u * nb);
    }

    // ===================== P4: per-S1-node agg + LN + ELU ===================
    {
        // preload va1 + vb1 into shared (once)
        for (int u = t; u < 8 * INF; u += 256)
            ((float*)s_va1)[u] = ((const float*)g_va1)[u];
        if (t < 8) s_vb1s[t] = g_vb1[t];
        __syncthreads();

        int s0 = min(g_s1_cnt[0], MAX_S1), s1c = min(g_s1_cnt[1], MAX_S1);
        int tot = s0 + s1c;
        int h = wid >> 1;   // head owned by this warp in the matvec (const)

        for (int task = bi; task < tot; task += nb) {
            int b = (task >= s0);
            int p = b ? task - s0 : task;
            int node = g_s1_list[b][p];
            if (t == 0) s_mcnt = 0;
            __syncthreads();

            // match scan
            int ecnt = min(g_e1_cnt[b], MAX_E1);
            for (int i = t; i < ecnt; i += 256) {
                if (g_e1_src[b][i] == node) {
                    int m = atomicAdd(&s_mcnt, 1);
                    if (m < MAX_MATCH) s_md[m] = g_e1_dst[b][i];
                }
            }
            __syncthreads();
            int mc = min(s_mcnt, MAX_MATCH);

            // psn (per-warp redundant): ps1[node][h] = emb.va1[h] + vb1[h]
            float p0, p1, p2, p3;
            {
                const float4* er = (const float4*)(embed + (size_t)node * INF);
                float4 e0 = er[lane], e1 = er[lane + 32];
                p0 = dot44(e0, ((float4*)s_va1[0])[lane]) + dot44(e1, ((float4*)s_va1[0])[lane + 32]);
                p1 = dot44(e0, ((float4*)s_va1[1])[lane]) + dot44(e1, ((float4*)s_va1[1])[lane + 32]);
                p2 = dot44(e0, ((float4*)s_va1[2])[lane]) + dot44(e1, ((float4*)s_va1[2])[lane + 32]);
                p3 = dot44(e0, ((float4*)s_va1[3])[lane]) + dot44(e1, ((float4*)s_va1[3])[lane + 32]);
                warpsum4(p0, p1, p2, p3);
                p0 += s_vb1s[0]; p1 += s_vb1s[1]; p2 += s_vb1s[2]; p3 += s_vb1s[3];
            }

            // per-match attention weights (warps parallel over matches)
            for (int m = wid; m < mc; m += 8) {
                int d = s_md[m];
                const float4* dr = (const float4*)(embed + (size_t)d * INF);
                float4 d0 = dr[lane], d1 = dr[lane + 32];
                float q0 = dot44(d0, ((float4*)s_va1[4])[lane]) + dot44(d1, ((float4*)s_va1[4])[lane + 32]);
                float q1 = dot44(d0, ((float4*)s_va1[5])[lane]) + dot44(d1, ((float4*)s_va1[5])[lane + 32]);
                float q2 = dot44(d0, ((float4*)s_va1[6])[lane]) + dot44(d1, ((float4*)s_va1[6])[lane + 32]);
                float q3 = dot44(d0, ((float4*)s_va1[7])[lane]) + dot44(d1, ((float4*)s_va1[7])[lane + 32]);
                warpsum4(q0, q1, q2, q3);
                if (lane == 0) {
                    float s, l;
                    s = p0 + q0 + s_vb1s[4]; l = s > 0.f ? s : 0.2f * s; s_me[m][0] = __expf(l * INV_SCALE);
                    s = p1 + q1 + s_vb1s[5]; l = s > 0.f ? s : 0.2f * s; s_me[m][1] = __expf(l * INV_SCALE);
                    s = p2 + q2 + s_vb1s[6]; l = s > 0.f ? s : 0.2f * s; s_me[m][2] = __expf(l * INV_SCALE);
                    s = p3 + q3 + s_vb1s[7]; l = s > 0.f ? s : 0.2f * s; s_me[m][3] = __expf(l * INV_SCALE);
                }
            }
            __syncthreads();

            // rowsums
            if (t < NH) {
                float r = 0.f;
                for (int m = 0; m < mc; m++) r += s_me[m][t];
                s_rsT[t] = r;
                s_rs[t] = (r == 0.f) ? 1.f : r;
            }
            // z_h[t] = sum_m e_mh * embed[dst_m][t]
            float z0 = 0.f, z1 = 0.f, z2 = 0.f, z3 = 0.f;
            for (int m = 0; m < mc; m++) {
                float ev = embed[(size_t)s_md[m] * INF + t];
                float4 me = *(const float4*)s_me[m];
                z0 += me.x * ev; z1 += me.y * ev; z2 += me.z * ev; z3 += me.w * ev;
            }
            s_z[0][t] = z0; s_z[1][t] = z1; s_z[2][t] = z2; s_z[3][t] = z3;
            __syncthreads();

            // matvec: hp[o512] = (z_h . W1row + rsT_h*b1) / rs_h, 4 outs/iter
            float rsT = s_rsT[h], invrs = 1.f / s_rs[h];
            const float4* z4 = (const float4*)s_z[h];
            float4 za = z4[lane], zb = z4[lane + 32];
            for (int og = 0; og < 64; og += 4) {
                int obase = wid * 64 + og;
                int o = obase & 127;
                const float4* w0 = (const float4*)(W1 + (size_t)(h * HID + o + 0) * INF);
                const float4* w1 = (const float4*)(W1 + (size_t)(h * HID + o + 1) * INF);
                const float4* w2 = (const float4*)(W1 + (size_t)(h * HID + o + 2) * INF);
                const float4* w3 = (const float4*)(W1 + (size_t)(h * HID + o + 3) * INF);
                float v0 = dot44(w0[lane], za) + dot44(w0[lane + 32], zb);
                float v1 = dot44(w1[lane], za) + dot44(w1[lane + 32], zb);
                float v2 = dot44(w2[lane], za) + dot44(w2[lane + 32], zb);
                float v3 = dot44(w3[lane], za) + dot44(w3[lane + 32], zb);
                warpsum4(v0, v1, v2, v3);
                if (lane == 0) {
                    const float* bb = b1 + h * HID + o;
                    s_ov[obase + 0] = (v0 + rsT * bb[0]) * invrs;
                    s_ov[obase + 1] = (v1 + rsT * bb[1]) * invrs;
                    s_ov[obase + 2] = (v2 + rsT * bb[2]) * invrs;
                    s_ov[obase + 3] = (v3 + rsT * bb[3]) * invrs;
                }
            }
            __syncthreads();

            // LayerNorm(ddof=1, eps on std) + ELU
            float v0 = s_ov[t], v1 = s_ov[t + 256];
            float mean = blockreduce256(v0 + v1, s_red) * (1.f / 512.f);
            float d0 = v0 - mean, d1 = v1 - mean;
            float var = blockreduce256(d0 * d0 + d1 * d1, s_red) * (1.f / 511.f);
            float inv = 1.f / (sqrtf(var) + 1e-6f);
            float y0 = g1[t] * d0 * inv + bn1[t];
            float y1 = g1[t + 256] * d1 * inv + bn1[t + 256];
            y0 = y0 > 0.f ? y0 : __expf(y0) - 1.f;
            y1 = y1 > 0.f ? y1 : __expf(y1) - 1.f;
            g_hln[b][p][t] = y0;
            g_hln[b][p][t + 256] = y1;
            __syncthreads();
        }
    }
    gbar(4u * nb);

    // ===================== P6: final layer-2 at LASTN =======================
    if (bi < NB) {
        int b = bi;
        int ec = min(g_d2_cnt[b], MAX_D2);
        int h = wid >> 1;

        // ps2[LASTN] per warp (s1 idx 0)
        float r0, r1, r2, r3;
        {
            const float4* hr = (const float4*)g_hln[b][0];
            float4 x0 = hr[lane], x1 = hr[lane + 32], x2 = hr[lane + 64], x3 = hr[lane + 96];
            const float4* v0p = (const float4*)g_va2[0];
            const float4* v1p = (const float4*)g_va2[1];
            const float4* v2p = (const float4*)g_va2[2];
            const float4* v3p = (const float4*)g_va2[3];
            r0 = dot44(x0, v0p[lane]) + dot44(x1, v0p[lane + 32]) + dot44(x2, v0p[lane + 64]) + dot44(x3, v0p[lane + 96]);
            r1 = dot44(x0, v1p[lane]) + dot44(x1, v1p[lane + 32]) + dot44(x2, v1p[lane + 64]) + dot44(x3, v1p[lane + 96]);
            r2 = dot44(x0, v2p[lane]) + dot44(x1, v2p[lane + 32]) + dot44(x2, v2p[lane + 64]) + dot44(x3, v2p[lane + 96]);
            r3 = dot44(x0, v3p[lane]) + dot44(x1, v3p[lane + 32]) + dot44(x2, v3p[lane + 64]) + dot44(x3, v3p[lane + 96]);
            warpsum4(r0, r1, r2, r3);
            r0 += g_vb2[0]; r1 += g_vb2[1]; r2 += g_vb2[2]; r3 += g_vb2[3];
        }

        // per-edge weights (warps parallel)
        for (int i = wid; i < ec; i += 8) {
            int d = g_d2_dst[b][i];
            int pd = g_s1_idx[b][d];
            const float4* hr = (const float4*)g_hln[b][pd];
            float4 x0 = hr[lane], x1 = hr[lane + 32], x2 = hr[lane + 64], x3 = hr[lane + 96];
            const float4* v4p = (const float4*)g_va2[4];
            const float4* v5p = (const float4*)g_va2[5];
            const float4* v6p = (const float4*)g_va2[6];
            const float4* v7p = (const float4*)g_va2[7];
            float q0 = dot44(x0, v4p[lane]) + dot44(x1, v4p[lane + 32]) + dot44(x2, v4p[lane + 64]) + dot44(x3, v4p[lane + 96]);
            float q1 = dot44(x0, v5p[lane]) + dot44(x1, v5p[lane + 32]) + dot44(x2, v5p[lane + 64]) + dot44(x3, v5p[lane + 96]);
            float q2 = dot44(x0, v6p[lane]) + dot44(x1, v6p[lane + 32]) + dot44(x2, v6p[lane + 64]) + dot44(x3, v6p[lane + 96]);
            float q3 = dot44(x0, v7p[lane]) + dot44(x1, v7p[lane + 32]) + dot44(x2, v7p[lane + 64]) + dot44(x3, v7p[lane + 96]);
            warpsum4(q0, q1, q2, q3);
            if (lane == 0) {
                s_md2[i] = pd;
                float s, l;
                s = r0 + q0 + g_vb2[4]; l = s > 0.f ? s : 0.2f * s; s_e2[i][0] = __expf(l * INV_SCALE);
                s = r1 + q1 + g_vb2[5]; l = s > 0.f ? s : 0.2f * s; s_e2[i][1] = __expf(l * INV_SCALE);
                s = r2 + q2 + g_vb2[6]; l = s > 0.f ? s : 0.2f * s; s_e2[i][2] = __expf(l * INV_SCALE);
                s = r3 + q3 + g_vb2[7]; l = s > 0.f ? s : 0.2f * s; s_e2[i][3] = __expf(l * INV_SCALE);
            }
        }
        __syncthreads();

        // rowsums
        if (t < NH) {
            float r = 0.f;
            for (int i = 0; i < ec; i++) r += s_e2[i][t];
            s_rsT[t] = r;
            s_rs[t] = (r == 0.f) ? 1.f : r;
        }
        // z2_h = sum e * hln[dst]
        float za0 = 0.f, za1 = 0.f, za2 = 0.f, za3 = 0.f;
        float zb0 = 0.f, zb1 = 0.f, zb2 = 0.f, zb3 = 0.f;
        for (int i = 0; i < ec; i++) {
            int pd = s_md2[i];
            float hv0 = g_hln[b][pd][t];
            float hv1 = g_hln[b][pd][t + 256];
            float4 me = *(const float4*)s_e2[i];
            za0 += me.x * hv0; za1 += me.y * hv0; za2 += me.z * hv0; za3 += me.w * hv0;
            zb0 += me.x * hv1; zb1 += me.y * hv1; zb2 += me.z * hv1; zb3 += me.w * hv1;
        }
        s_z2[0][t] = za0; s_z2[1][t] = za1; s_z2[2][t] = za2; s_z2[3][t] = za3;
        s_z2[0][t + 256] = zb0; s_z2[1][t + 256] = zb1; s_z2[2][t + 256] = zb2; s_z2[3][t + 256] = zb3;
        __syncthreads();

        // matvec dot-512 per output (4 outs/iter per warp)
        float rsT = s_rsT[h], invrs = 1.f / s_rs[h];
        const float4* z4 = (const float4*)s_z2[h];
        float4 zc0 = z4[lane], zc1 = z4[lane + 32], zc2 = z4[lane + 64], zc3 = z4[lane + 96];
        for (int og = 0; og < 64; og += 4) {
            int obase = wid * 64 + og;
            int o = obase & 127;
            float v[4];
#pragma unroll
            for (int j = 0; j < 4; j++) {
                const float4* wr = (const float4*)(W2 + (size_t)(h * HID + o + j) * HD);
                v[j] = dot44(wr[lane], zc0) + dot44(wr[lane + 32], zc1)
                     + dot44(wr[lane + 64], zc2) + dot44(wr[lane + 96], zc3);
            }
            warpsum4(v[0], v[1], v[2], v[3]);
            if (lane == 0) {
                const float* bb = b2 + h * HID + o;
                s_hp2[obase + 0] = (v[0] + rsT * bb[0]) * invrs;
                s_hp2[obase + 1] = (v[1] + rsT * bb[1]) * invrs;
                s_hp2[obase + 2] = (v[2] + rsT * bb[2]) * invrs;
                s_hp2[obase + 3] = (v[3] + rsT * bb[3]) * invrs;
            }
        }
        __syncthreads();

        // mean over heads + LN(128) + ReLU + projection
        float v = 0.f;
        if (t < 128)
            v = 0.25f * (s_hp2[t] + s_hp2[128 + t] + s_hp2[256 + t] + s_hp2[384 + t]);
        float mean = blockreduce256(v, s_red) * (1.f / 128.f);
        float dv = (t < 128) ? v - mean : 0.f;
        float var = blockreduce256(dv * dv, s_red) * (1.f / 127.f);
        float inv = 1.f / (sqrtf(var) + 1e-6f);
        float y = 0.f;
        if (t < 128) {
            y = g2[t] * dv * inv + bn2[t];
            y = y > 0.f ? y : 0.f;
        }
        float c0 = blockreduce256((t < 128) ? y * Vw[t] : 0.f, s_red);
        float c1 = blockreduce256((t < 128) ? y * Vw[HID + t] : 0.f, s_red);
        if (t == 0) {
            out[b * 2 + 0] = c0 + Vb[0];
            out[b * 2 + 1] = c1 + Vb[1];
        }
    }

    // final arrive; last block resets barrier for the next graph replay
    __syncthreads();
    if (t == 0) {
        __threadfence();
        unsigned old = atomicAdd(&g_bar, 1u);
        if (old == 5u * nb - 1u) atomicExch(&g_bar, 0u);
    }
}

// ------------------------------- launcher ----------------------------------
extern "C" void kernel_launch(void* const* d_in, const int* in_sizes, int n_in,
                              void* d_out, int out_size) {
    const int*   edge_in  = (const int*)d_in[0];
    const int*   edge_out = (const int*)d_in[1];
    const float* embed    = (const float*)d_in[2];
    const float* W1       = (const float*)d_in[3];
    const float* b1       = (const float*)d_in[4];
    const float* a1       = (const float*)d_in[5];
    const float* g1       = (const float*)d_in[6];
    const float* bn1      = (const float*)d_in[7];
    const float* W2       = (const float*)d_in[8];
    const float* b2       = (const float*)d_in[9];
    const float* a2       = (const float*)d_in[10];
    const float* g2       = (const float*)d_in[11];
    const float* bn2      = (const float*)d_in[12];
    const float* Vw       = (const float*)d_in[13];
    const float* Vb       = (const float*)d_in[14];
    float* out = (float*)d_out;

    int nsm = 0;
    cudaDeviceGetAttribute(&nsm, cudaDevAttrMultiProcessorCount, 0);
    if (nsm <= 0) nsm = 132;
    int occ = 0;
    cudaOccupancyMaxActiveBlocksPerMultiprocessor(&occ, fused, 256, 0);
    if (occ < 1) occ = 1;
    if (occ > 2) occ = 2;

    fused<<<nsm * occ, 256>>>(edge_in, edge_out, embed, W1, b1, a1, g1, bn1,
                              W2, b2, a2, g2, bn2, Vw, Vb, out);
}

// round 10
// speedup vs baseline: 1.1119x; 1.1119x over previous
#include <cuda_runtime.h>
#include <math.h>

// ---------------------------------------------------------------------------
// GAT_652835029007 — round 10: round-9 + L2 prefetch (W1/W2 by va-blocks,
// edge_in during P1) + unroll-2 on latency-chained loops.
//   init -> bar1 -> { va-blocks: va/vb then prefetch W1+W2 (arrive at bar2),
//                     scan-blocks: P1 edge_out scan (+edge_in prefetch)
//                     -> bar2 -> P2 edge_in }
//   -> bar3 -> P4 per-S1-node agg+LN+ELU -> bar4 -> P6 final -> arrive.
// ---------------------------------------------------------------------------

#define NNODE 20001
#define LASTN 20000
#define INF   256
#define HID   128
#define NH    4
#define HD    512
#define NB    2
#define NE    500000
#define NE8   62500
#define BMW   626
#define MAX_D2    512
#define MAX_E1    65536
#define MAX_S1    1024
#define MAX_MATCH 512
#define NVA   14
#define INV_SCALE 0.044194173824159216f   // 1/sqrt(512)

// ------------------------------- scratch -----------------------------------
__device__ unsigned g_bar;                 // zero-init; reset by last arriver
__device__ int      g_sink;                // DCE-prevention sink (never read)
__device__ int      g_d2_cnt[NB];
__device__ int      g_d2_dst[NB][MAX_D2];
__device__ unsigned g_s1_bm[NB][BMW];
__device__ int      g_s1_cnt[NB];
__device__ int      g_s1_list[NB][MAX_S1];
__device__ int      g_s1_idx[NB][NNODE];
__device__ int      g_e1_cnt[NB];
__device__ int      g_e1_src[NB][MAX_E1], g_e1_dst[NB][MAX_E1];
__device__ __align__(16) float g_hln[NB][MAX_S1][HD];
__device__ __align__(16) float g_va1[8][INF];   // [h]=src-half, [4+h]=dst-half
__device__ __align__(16) float g_va2[8][HD];
__device__ float    g_vb1[8], g_vb2[8];

// ------------------------------- helpers -----------------------------------
__device__ __forceinline__ float dot44(float4 a, float4 b) {
    return a.x * b.x + a.y * b.y + a.z * b.z + a.w * b.w;
}

__device__ __forceinline__ void warpsum4(float& a, float& b, float& c, float& d) {
#pragma unroll
    for (int off = 16; off; off >>= 1) {
        a += __shfl_xor_sync(0xffffffffu, a, off);
        b += __shfl_xor_sync(0xffffffffu, b, off);
        c += __shfl_xor_sync(0xffffffffu, c, off);
        d += __shfl_xor_sync(0xffffffffu, d, off);
    }
}

__device__ __forceinline__ float blockreduce256(float v, float* sred) {
    int t = threadIdx.x;
    sred[t] = v; __syncthreads();
#pragma unroll
    for (int s = 128; s > 0; s >>= 1) {
        if (t < s) sred[t] += sred[t + s];
        __syncthreads();
    }
    float r = sred[0]; __syncthreads();
    return r;
}

__device__ __forceinline__ void gbar_arrive() {
    __syncthreads();
    if (threadIdx.x == 0) {
        __threadfence();
        atomicAdd(&g_bar, 1u);
    }
    __syncthreads();
}

__device__ __forceinline__ void gbar(unsigned target) {
    __syncthreads();
    if (threadIdx.x == 0) {
        __threadfence();
        atomicAdd(&g_bar, 1u);
        while (*(volatile unsigned*)&g_bar < target) __nanosleep(32);
        __threadfence();
    }
    __syncthreads();
}

// ------------------------------- fused kernel -------------------------------
__global__ void __launch_bounds__(256, 2) fused(
    const int* __restrict__ ei, const int* __restrict__ eo,
    const float* __restrict__ embed,
    const float* __restrict__ W1, const float* __restrict__ b1,
    const float* __restrict__ a1,
    const float* __restrict__ g1, const float* __restrict__ bn1,
    const float* __restrict__ W2, const float* __restrict__ b2,
    const float* __restrict__ a2,
    const float* __restrict__ g2, const float* __restrict__ bn2,
    const float* __restrict__ Vw, const float* __restrict__ Vb,
    float* __restrict__ out)
{
    int t = threadIdx.x;
    int lane = t & 31, wid = t >> 5;
    unsigned nb = gridDim.x;
    int bi = blockIdx.x;
    int gtid = bi * 256 + t;
    int nth = nb * 256;

    __shared__ __align__(16) float s_red[256];
    __shared__ float s_rs[NH], s_rsT[NH];
    __shared__ int   s_mcnt;
    __shared__ __align__(16) float s_va1[8][INF];
    __shared__ float s_vb1s[8];
    __shared__ __align__(16) char s_mem[20480];
    // P4 views
    int*   s_md = (int*)s_mem;                           // [512]      2KB
    float (*s_me)[NH] = (float(*)[NH])(s_mem + 2048);    // [512][4]   8KB
    float (*s_z)[INF] = (float(*)[INF])(s_mem + 10240);  // [4][256]   4KB
    float* s_ov = (float*)(s_mem + 14336);               // [512]      2KB
    // P6 views
    float (*s_z2)[HD] = (float(*)[HD])(s_mem);           // [4][512]   8KB
    float (*s_e2)[NH] = (float(*)[NH])(s_mem + 8192);    // [512][4]   8KB
    int*   s_md2 = (int*)(s_mem + 16384);                // [512]      2KB
    float* s_hp2 = s_ov;

    // ===================== init (all blocks, tiny) ==========================
    for (int i = gtid; i < NB * BMW; i += nth) {
        int b = i / BMW, w = i - b * BMW;
        g_s1_bm[b][w] = (w == (LASTN >> 5)) ? (1u << (LASTN & 31)) : 0u;
    }
    if (bi == nb - 1 && t == 0) {
        for (int b = 0; b < NB; b++) {
            g_d2_cnt[b] = 0; g_e1_cnt[b] = 0;
            g_s1_cnt[b] = 1;
            g_s1_list[b][0] = LASTN; g_s1_idx[b][LASTN] = 0;
        }
    }
    gbar(1u * nb);

    // ===================== window 1+2: va blocks vs scan blocks =============
    if (bi < NVA) {
        // arrive-only at bar2: nothing in P1/P2 depends on va outputs.
        gbar_arrive();
        if (bi < 4) {
            int h = bi, k = t;
            const float* W = W1 + (size_t)h * HID * INF + k;
            const float* as = a1 + h * 2 * HID;
            const float* ad = as + HID;
            float s0 = 0.f, s1_ = 0.f, d0 = 0.f, d1_ = 0.f;
#pragma unroll 16
            for (int o = 0; o < HID; o += 2) {
                float w0 = W[(o + 0) * INF];
                float w1 = W[(o + 1) * INF];
                s0 += w0 * as[o]; s1_ += w1 * as[o + 1];
                d0 += w0 * ad[o]; d1_ += w1 * ad[o + 1];
            }
            g_va1[h][k] = s0 + s1_;
            g_va1[4 + h][k] = d0 + d1_;
        } else if (bi < 12) {
            int u = bi - 4;
            int h = u >> 1, k = (u & 1) * 256 + t;
            const float* W = W2 + (size_t)h * HID * HD + k;
            const float* as = a2 + h * 2 * HID;
            const float* ad = as + HID;
            float s0 = 0.f, s1_ = 0.f, d0 = 0.f, d1_ = 0.f;
#pragma unroll 16
            for (int o = 0; o < HID; o += 2) {
                float w0 = W[(o + 0) * HD];
                float w1 = W[(o + 1) * HD];
                s0 += w0 * as[o]; s1_ += w1 * as[o + 1];
                d0 += w0 * ad[o]; d1_ += w1 * ad[o + 1];
            }
            g_va2[h][k] = s0 + s1_;
            g_va2[4 + h][k] = d0 + d1_;
        } else {
            int which = (bi == 13);
            int idx = wid, h = idx & 3, sd = idx >> 2;
            const float* bb = (which ? b2 : b1) + h * HID;
            const float* av = (which ? a2 : a1) + h * 2 * HID + sd * HID;
            float p = 0.f;
            for (int o = lane; o < HID; o += 32) p += bb[o] * av[o];
#pragma unroll
            for (int off = 16; off; off >>= 1) p += __shfl_xor_sync(0xffffffffu, p, off);
            if (lane == 0) { if (which) g_vb2[idx] = p; else g_vb1[idx] = p; }
        }

        // ---- L2-warm W1 (32768 float4) + W2 (65536 float4) while scans run
        {
            float acc = 0.f;
            const float4* W1v = (const float4*)W1;
            const float4* W2v = (const float4*)W2;
            for (int u = bi * 256 + t; u < 98304; u += NVA * 256) {
                float4 v = (u < 32768) ? W1v[u] : W2v[u - 32768];
                acc += v.x + v.w;
            }
            if (__float_as_int(acc) == 0x7f800001) g_sink = 1;   // never in practice
        }
        // full arrive+wait at bar3 (va results now published)
        gbar(3u * nb);
    } else {
        int sid = (bi - NVA) * 256 + t;
        int snth = (nb - NVA) * 256;

        // -------- P1: scan edge_out for src == LASTN (+ edge_in L2 prefetch)
        int psum = 0;
        for (int u = sid; u < NB * NE8; u += snth) {
            int b = (u >= NE8);
            int i8 = (b ? u - NE8 : u) * 8;
            const int* base = eo + (size_t)b * 2 * NE;
            int4 sA = *(const int4*)(base + i8);
            int4 sB = *(const int4*)(base + i8 + 4);
            // prefetch edge_in src words into L2 (independent, hidden)
            const int* pbase = ei + (size_t)b * 2 * NE;
            int4 pA = *(const int4*)(pbase + i8);
            int4 pB = *(const int4*)(pbase + i8 + 4);
            psum += pA.x ^ pB.w;
            int sv[8] = {sA.x, sA.y, sA.z, sA.w, sB.x, sB.y, sB.z, sB.w};
#pragma unroll
            for (int j = 0; j < 8; j++) {
                if (sv[j] == LASTN) {
                    int dst = base[NE + i8 + j];
                    int p = atomicAdd(&g_d2_cnt[b], 1);
                    if (p < MAX_D2) g_d2_dst[b][p] = dst;
                    unsigned m = 1u << (dst & 31);
                    unsigned old = atomicOr(&g_s1_bm[b][dst >> 5], m);
                    if (!(old & m)) {
                        int q = atomicAdd(&g_s1_cnt[b], 1);
                        if (q < MAX_S1) { g_s1_list[b][q] = dst; g_s1_idx[b][dst] = q; }
                    }
                }
            }
        }
        if (psum == 0x13579bdf) g_sink = 1;   // keep prefetch loads alive
        gbar(2u * nb);

        // -------- P2: scan edge_in for src in S1 (8 ints/iter, L2-warm) -----
        for (int u = sid; u < NB * NE8; u += snth) {
            int b = (u >= NE8);
            int i8 = (b ? u - NE8 : u) * 8;
            const int* base = ei + (size_t)b * 2 * NE;
            int4 sA = *(const int4*)(base + i8);
            int4 sB = *(const int4*)(base + i8 + 4);
            int sv[8] = {sA.x, sA.y, sA.z, sA.w, sB.x, sB.y, sB.z, sB.w};
#pragma unroll
            for (int j = 0; j < 8; j++) {
                int s = sv[j];
                if ((g_s1_bm[b][s >> 5] >> (s & 31)) & 1u) {
                    int p = atomicAdd(&g_e1_cnt[b], 1);
                    if (p < MAX_E1) {
                        g_e1_src[b][p] = s;
                        g_e1_dst[b][p] = base[NE + i8 + j];
                    }
                }
            }
        }
        gbar(3u * nb);
    }

    // ===================== P4: per-S1-node agg + LN + ELU ===================
    {
        for (int u = t; u < 8 * INF; u += 256)
            ((float*)s_va1)[u] = ((const float*)g_va1)[u];
        if (t < 8) s_vb1s[t] = g_vb1[t];
        __syncthreads();

        int s0 = min(g_s1_cnt[0], MAX_S1), s1c = min(g_s1_cnt[1], MAX_S1);
        int tot = s0 + s1c;
        int h = wid >> 1;

        for (int task = bi; task < tot; task += nb) {
            int b = (task >= s0);
            int p = b ? task - s0 : task;
            int node = g_s1_list[b][p];
            if (t == 0) s_mcnt = 0;
            __syncthreads();

            // match scan
            int ecnt = min(g_e1_cnt[b], MAX_E1);
            for (int i = t; i < ecnt; i += 256) {
                if (g_e1_src[b][i] == node) {
                    int m = atomicAdd(&s_mcnt, 1);
                    if (m < MAX_MATCH) s_md[m] = g_e1_dst[b][i];
                }
            }
            __syncthreads();
            int mc = min(s_mcnt, MAX_MATCH);

            // psn (per-warp redundant)
            float p0, p1, p2, p3;
            {
                const float4* er = (const float4*)(embed + (size_t)node * INF);
                float4 e0 = er[lane], e1 = er[lane + 32];
                p0 = dot44(e0, ((float4*)s_va1[0])[lane]) + dot44(e1, ((float4*)s_va1[0])[lane + 32]);
                p1 = dot44(e0, ((float4*)s_va1[1])[lane]) + dot44(e1, ((float4*)s_va1[1])[lane + 32]);
                p2 = dot44(e0, ((float4*)s_va1[2])[lane]) + dot44(e1, ((float4*)s_va1[2])[lane + 32]);
                p3 = dot44(e0, ((float4*)s_va1[3])[lane]) + dot44(e1, ((float4*)s_va1[3])[lane + 32]);
                warpsum4(p0, p1, p2, p3);
                p0 += s_vb1s[0]; p1 += s_vb1s[1]; p2 += s_vb1s[2]; p3 += s_vb1s[3];
            }

            // per-match attention weights (warps parallel over matches)
#pragma unroll 2
            for (int m = wid; m < mc; m += 8) {
                int d = s_md[m];
                const float4* dr = (const float4*)(embed + (size_t)d * INF);
                float4 d0 = dr[lane], d1 = dr[lane + 32];
                float q0 = dot44(d0, ((float4*)s_va1[4])[lane]) + dot44(d1, ((float4*)s_va1[4])[lane + 32]);
                float q1 = dot44(d0, ((float4*)s_va1[5])[lane]) + dot44(d1, ((float4*)s_va1[5])[lane + 32]);
                float q2 = dot44(d0, ((float4*)s_va1[6])[lane]) + dot44(d1, ((float4*)s_va1[6])[lane + 32]);
                float q3 = dot44(d0, ((float4*)s_va1[7])[lane]) + dot44(d1, ((float4*)s_va1[7])[lane + 32]);
                warpsum4(q0, q1, q2, q3);
                if (lane == 0) {
                    float s, l;
                    s = p0 + q0 + s_vb1s[4]; l = s > 0.f ? s : 0.2f * s; s_me[m][0] = __expf(l * INV_SCALE);
                    s = p1 + q1 + s_vb1s[5]; l = s > 0.f ? s : 0.2f * s; s_me[m][1] = __expf(l * INV_SCALE);
                    s = p2 + q2 + s_vb1s[6]; l = s > 0.f ? s : 0.2f * s; s_me[m][2] = __expf(l * INV_SCALE);
                    s = p3 + q3 + s_vb1s[7]; l = s > 0.f ? s : 0.2f * s; s_me[m][3] = __expf(l * INV_SCALE);
                }
            }
            __syncthreads();

            // rowsums
            if (t < NH) {
                float r = 0.f;
                for (int m = 0; m < mc; m++) r += s_me[m][t];
                s_rsT[t] = r;
                s_rs[t] = (r == 0.f) ? 1.f : r;
            }
            // z_h[t] = sum_m e_mh * embed[dst_m][t]
            float z0 = 0.f, z1 = 0.f, z2 = 0.f, z3 = 0.f;
            for (int m = 0; m < mc; m++) {
                float ev = embed[(size_t)s_md[m] * INF + t];
                float4 me = *(const float4*)s_me[m];
                z0 += me.x * ev; z1 += me.y * ev; z2 += me.z * ev; z3 += me.w * ev;
            }
            s_z[0][t] = z0; s_z[1][t] = z1; s_z[2][t] = z2; s_z[3][t] = z3;
            __syncthreads();

            // matvec (W1 rows now L2-warm): 4 outs/iter, unroll 2
            float rsT = s_rsT[h], invrs = 1.f / s_rs[h];
            const float4* z4 = (const float4*)s_z[h];
            float4 za = z4[lane], zb = z4[lane + 32];
#pragma unroll 2
            for (int og = 0; og < 64; og += 4) {
                int obase = wid * 64 + og;
                int o = obase & 127;
                const float4* w0 = (const float4*)(W1 + (size_t)(h * HID + o + 0) * INF);
                const float4* w1 = (const float4*)(W1 + (size_t)(h * HID + o + 1) * INF);
                const float4* w2 = (const float4*)(W1 + (size_t)(h * HID + o + 2) * INF);
                const float4* w3 = (const float4*)(W1 + (size_t)(h * HID + o + 3) * INF);
                float v0 = dot44(w0[lane], za) + dot44(w0[lane + 32], zb);
                float v1 = dot44(w1[lane], za) + dot44(w1[lane + 32], zb);
                float v2 = dot44(w2[lane], za) + dot44(w2[lane + 32], zb);
                float v3 = dot44(w3[lane], za) + dot44(w3[lane + 32], zb);
                warpsum4(v0, v1, v2, v3);
                if (lane == 0) {
                    const float* bb = b1 + h * HID + o;
                    s_ov[obase + 0] = (v0 + rsT * bb[0]) * invrs;
                    s_ov[obase + 1] = (v1 + rsT * bb[1]) * invrs;
                    s_ov[obase + 2] = (v2 + rsT * bb[2]) * invrs;
                    s_ov[obase + 3] = (v3 + rsT * bb[3]) * invrs;
                }
            }
            __syncthreads();

            // LayerNorm(ddof=1, eps on std) + ELU
            float v0 = s_ov[t], v1 = s_ov[t + 256];
            float mean = blockreduce256(v0 + v1, s_red) * (1.f / 512.f);
            float d0 = v0 - mean, d1 = v1 - mean;
            float var = blockreduce256(d0 * d0 + d1 * d1, s_red) * (1.f / 511.f);
            float inv = 1.f / (sqrtf(var) + 1e-6f);
            float y0 = g1[t] * d0 * inv + bn1[t];
            float y1 = g1[t + 256] * d1 * inv + bn1[t + 256];
            y0 = y0 > 0.f ? y0 : __expf(y0) - 1.f;
            y1 = y1 > 0.f ? y1 : __expf(y1) - 1.f;
            g_hln[b][p][t] = y0;
            g_hln[b][p][t + 256] = y1;
            __syncthreads();
        }
    }
    gbar(4u * nb);

    // ===================== P6: final layer-2 at LASTN =======================
    if (bi < NB) {
        int b = bi;
        int ec = min(g_d2_cnt[b], MAX_D2);
        int h = wid >> 1;

        // ps2[LASTN] per warp (s1 idx 0)
        float r0, r1, r2, r3;
        {
            const float4* hr = (const float4*)g_hln[b][0];
            float4 x0 = hr[lane], x1 = hr[lane + 32], x2 = hr[lane + 64], x3 = hr[lane + 96];
            const float4* v0p = (const float4*)g_va2[0];
            const float4* v1p = (const float4*)g_va2[1];
            const float4* v2p = (const float4*)g_va2[2];
            const float4* v3p = (const float4*)g_va2[3];
            r0 = dot44(x0, v0p[lane]) + dot44(x1, v0p[lane + 32]) + dot44(x2, v0p[lane + 64]) + dot44(x3, v0p[lane + 96]);
            r1 = dot44(x0, v1p[lane]) + dot44(x1, v1p[lane + 32]) + dot44(x2, v1p[lane + 64]) + dot44(x3, v1p[lane + 96]);
            r2 = dot44(x0, v2p[lane]) + dot44(x1, v2p[lane + 32]) + dot44(x2, v2p[lane + 64]) + dot44(x3, v2p[lane + 96]);
            r3 = dot44(x0, v3p[lane]) + dot44(x1, v3p[lane + 32]) + dot44(x2, v3p[lane + 64]) + dot44(x3, v3p[lane + 96]);
            warpsum4(r0, r1, r2, r3);
            r0 += g_vb2[0]; r1 += g_vb2[1]; r2 += g_vb2[2]; r3 += g_vb2[3];
        }

        // per-edge weights (warps parallel, unroll 2)
#pragma unroll 2
        for (int i = wid; i < ec; i += 8) {
            int d = g_d2_dst[b][i];
            int pd = g_s1_idx[b][d];
            const float4* hr = (const float4*)g_hln[b][pd];
            float4 x0 = hr[lane], x1 = hr[lane + 32], x2 = hr[lane + 64], x3 = hr[lane + 96];
            const float4* v4p = (const float4*)g_va2[4];
            const float4* v5p = (const float4*)g_va2[5];
            const float4* v6p = (const float4*)g_va2[6];
            const float4* v7p = (const float4*)g_va2[7];
            float q0 = dot44(x0, v4p[lane]) + dot44(x1, v4p[lane + 32]) + dot44(x2, v4p[lane + 64]) + dot44(x3, v4p[lane + 96]);
            float q1 = dot44(x0, v5p[lane]) + dot44(x1, v5p[lane + 32]) + dot44(x2, v5p[lane + 64]) + dot44(x3, v5p[lane + 96]);
            float q2 = dot44(x0, v6p[lane]) + dot44(x1, v6p[lane + 32]) + dot44(x2, v6p[lane + 64]) + dot44(x3, v6p[lane + 96]);
            float q3 = dot44(x0, v7p[lane]) + dot44(x1, v7p[lane + 32]) + dot44(x2, v7p[lane + 64]) + dot44(x3, v7p[lane + 96]);
            warpsum4(q0, q1, q2, q3);
            if (lane == 0) {
                s_md2[i] = pd;
                float s, l;
                s = r0 + q0 + g_vb2[4]; l = s > 0.f ? s : 0.2f * s; s_e2[i][0] = __expf(l * INV_SCALE);
                s = r1 + q1 + g_vb2[5]; l = s > 0.f ? s : 0.2f * s; s_e2[i][1] = __expf(l * INV_SCALE);
                s = r2 + q2 + g_vb2[6]; l = s > 0.f ? s : 0.2f * s; s_e2[i][2] = __expf(l * INV_SCALE);
                s = r3 + q3 + g_vb2[7]; l = s > 0.f ? s : 0.2f * s; s_e2[i][3] = __expf(l * INV_SCALE);
            }
        }
        __syncthreads();

        // rowsums
        if (t < NH) {
            float r = 0.f;
            for (int i = 0; i < ec; i++) r += s_e2[i][t];
            s_rsT[t] = r;
            s_rs[t] = (r == 0.f) ? 1.f : r;
        }
        // z2_h = sum e * hln[dst]
        float za0 = 0.f, za1 = 0.f, za2 = 0.f, za3 = 0.f;
        float zb0 = 0.f, zb1 = 0.f, zb2 = 0.f, zb3 = 0.f;
        for (int i = 0; i < ec; i++) {
            int pd = s_md2[i];
            float hv0 = g_hln[b][pd][t];
            float hv1 = g_hln[b][pd][t + 256];
            float4 me = *(const float4*)s_e2[i];
            za0 += me.x * hv0; za1 += me.y * hv0; za2 += me.z * hv0; za3 += me.w * hv0;
            zb0 += me.x * hv1; zb1 += me.y * hv1; zb2 += me.z * hv1; zb3 += me.w * hv1;
        }
        s_z2[0][t] = za0; s_z2[1][t] = za1; s_z2[2][t] = za2; s_z2[3][t] = za3;
        s_z2[0][t + 256] = zb0; s_z2[1][t + 256] = zb1; s_z2[2][t + 256] = zb2; s_z2[3][t + 256] = zb3;
        __syncthreads();

        // matvec dot-512 per output (W2 rows L2-warm), unroll 2
        float rsT = s_rsT[h], invrs = 1.f / s_rs[h];
        const float4* z4 = (const float4*)s_z2[h];
        float4 zc0 = z4[lane], zc1 = z4[lane + 32], zc2 = z4[lane + 64], zc3 = z4[lane + 96];
#pragma unroll 2
        for (int og = 0; og < 64; og += 4) {
            int obase = wid * 64 + og;
            int o = obase & 127;
            float v[4];
#pragma unroll
            for (int j = 0; j < 4; j++) {
                const float4* wr = (const float4*)(W2 + (size_t)(h * HID + o + j) * HD);
                v[j] = dot44(wr[lane], zc0) + dot44(wr[lane + 32], zc1)
                     + dot44(wr[lane + 64], zc2) + dot44(wr[lane + 96], zc3);
            }
            warpsum4(v[0], v[1], v[2], v[3]);
            if (lane == 0) {
                const float* bb = b2 + h * HID + o;
                s_hp2[obase + 0] = (v[0] + rsT * bb[0]) * invrs;
                s_hp2[obase + 1] = (v[1] + rsT * bb[1]) * invrs;
                s_hp2[obase + 2] = (v[2] + rsT * bb[2]) * invrs;
                s_hp2[obase + 3] = (v[3] + rsT * bb[3]) * invrs;
            }
        }
        __syncthreads();

        // mean over heads + LN(128) + ReLU + projection
        float v = 0.f;
        if (t < 128)
            v = 0.25f * (s_hp2[t] + s_hp2[128 + t] + s_hp2[256 + t] + s_hp2[384 + t]);
        float mean = blockreduce256(v, s_red) * (1.f / 128.f);
        float dv = (t < 128) ? v - mean : 0.f;
        float var = blockreduce256(dv * dv, s_red) * (1.f / 127.f);
        float inv = 1.f / (sqrtf(var) + 1e-6f);
        float y = 0.f;
        if (t < 128) {
            y = g2[t] * dv * inv + bn2[t];
            y = y > 0.f ? y : 0.f;
        }
        float c0 = blockreduce256((t < 128) ? y * Vw[t] : 0.f, s_red);
        float c1 = blockreduce256((t < 128) ? y * Vw[HID + t] : 0.f, s_red);
        if (t == 0) {
            out[b * 2 + 0] = c0 + Vb[0];
            out[b * 2 + 1] = c1 + Vb[1];
        }
    }

    // final arrive; last block resets barrier for the next graph replay
    __syncthreads();
    if (t == 0) {
        __threadfence();
        unsigned old = atomicAdd(&g_bar, 1u);
        if (old == 5u * nb - 1u) atomicExch(&g_bar, 0u);
    }
}

// ------------------------------- launcher ----------------------------------
extern "C" void kernel_launch(void* const* d_in, const int* in_sizes, int n_in,
                              void* d_out, int out_size) {
    const int*   edge_in  = (const int*)d_in[0];
    const int*   edge_out = (const int*)d_in[1];
    const float* embed    = (const float*)d_in[2];
    const float* W1       = (const float*)d_in[3];
    const float* b1       = (const float*)d_in[4];
    const float* a1       = (const float*)d_in[5];
    const float* g1       = (const float*)d_in[6];
    const float* bn1      = (const float*)d_in[7];
    const float* W2       = (const float*)d_in[8];
    const float* b2       = (const float*)d_in[9];
    const float* a2       = (const float*)d_in[10];
    const float* g2       = (const float*)d_in[11];
    const float* bn2      = (const float*)d_in[12];
    const float* Vw       = (const float*)d_in[13];
    const float* Vb       = (const float*)d_in[14];
    float* out = (float*)d_out;

    int nsm = 0;
    cudaDeviceGetAttribute(&nsm, cudaDevAttrMultiProcessorCount, 0);
    if (nsm <= 0) nsm = 132;
    int occ = 0;
    cudaOccupancyMaxActiveBlocksPerMultiprocessor(&occ, fused, 256, 0);
    if (occ < 1) occ = 1;
    if (occ > 2) occ = 2;

    fused<<<nsm * occ, 256>>>(edge_in, edge_out, embed, W1, b1, a1, g1, bn1,
                              W2, b2, a2, g2, bn2, Vw, Vb, out);
}